// round 1
// baseline (speedup 1.0000x reference)
#include <cuda_runtime.h>
#include <math.h>

// Problem constants
#define BB    256
#define HH    6
#define NN    2048
#define MM    64
#define DIN   128
#define WFLAT 12288          // H*N
#define DCAT  12416
#define DOUT  384
#define Y_N   1152           // 3*DOUT
#define MEM_ELEMS 131072     // N*M per batch
#define OUT_MEM_TOTAL 33554432  // B*N*M

// GEMM config
#define SPLITK 8
#define KCHUNK 1552          // DCAT / SPLITK
#define KITERS 97            // KCHUNK / BKT
#define BKT 16
#define BMT 64
#define BNT 64
#define ASTR 20              // padded A stride (conflict-free frag loads)
#define BSTR 72              // padded B stride

// Scratch (static device memory; no allocation)
__device__ float g_Ypart[SPLITK * (size_t)BB * Y_N];  // 9.4 MB split-K partials
__device__ float g_Ks[BB * DOUT];
__device__ float g_Es[BB * DOUT];
__device__ float g_As[BB * DOUT];

__device__ __forceinline__ float f2tf(float f) {
    unsigned u;
    asm("cvt.rna.tf32.f32 %0, %1;" : "=r"(u) : "f"(f));
    return __uint_as_float(u);
}

#define MMA_TF32(c, a, b0, b1)                                                     \
    asm volatile(                                                                  \
        "mma.sync.aligned.m16n8k8.row.col.f32.tf32.tf32.f32 "                      \
        "{%0,%1,%2,%3},{%4,%5,%6,%7},{%8,%9},{%0,%1,%2,%3};"                       \
        : "+f"(c[0]), "+f"(c[1]), "+f"(c[2]), "+f"(c[3])                           \
        : "r"(a[0]), "r"(a[1]), "r"(a[2]), "r"(a[3]), "r"(b0), "r"(b1))

// ---------------------------------------------------------------------------
// K1: split-K tf32 GEMM  Y[256,1152] = x[256,12416] @ [Wk|We|Wa]
// x[b,k] = (k < 12288) ? w[b*12288+k] : inputs[b*128 + k-12288]
// grid (4, 18, 8), 128 threads
// ---------------------------------------------------------------------------
__global__ __launch_bounds__(128) void gemm_kernel(
    const float* __restrict__ xw, const float* __restrict__ xin,
    const float* __restrict__ Wk, const float* __restrict__ We,
    const float* __restrict__ Wa)
{
    __shared__ float As[2][BMT * ASTR];
    __shared__ float Bs[2][BKT * BSTR];

    const int tid = threadIdx.x;
    const int mt = blockIdx.x, nt = blockIdx.y, z = blockIdx.z;
    const int m0 = mt * BMT;
    const int mat = nt / 6;
    const int n0col = (nt % 6) * BNT;
    const float* __restrict__ Wp = (mat == 0) ? Wk : ((mat == 1) ? We : Wa);
    const int k0 = z * KCHUNK;

    const int wid = tid >> 5, lane = tid & 31;
    const int g = lane >> 2, t = lane & 3;
    const int wm = (wid & 1) * 32, wn = (wid >> 1) * 32;

    float acc[2][4][4];
#pragma unroll
    for (int i = 0; i < 2; i++)
#pragma unroll
        for (int j = 0; j < 4; j++)
#pragma unroll
            for (int q = 0; q < 4; q++) acc[i][j][q] = 0.0f;

    float4 ar[2], br[2];

#define GLOAD(it)                                                                  \
    do {                                                                           \
        int kb = k0 + (it) * BKT;                                                  \
        for (int i = 0; i < 2; i++) {                                              \
            int j = tid + i * 128;                                                 \
            int row = j >> 2;                                                      \
            int kg = kb + (j & 3) * 4;                                             \
            if (kg < WFLAT)                                                        \
                ar[i] = *(const float4*)(xw + (size_t)(m0 + row) * WFLAT + kg);    \
            else                                                                   \
                ar[i] = *(const float4*)(xin + (size_t)(m0 + row) * DIN +          \
                                         (kg - WFLAT));                            \
        }                                                                          \
        for (int i = 0; i < 2; i++) {                                              \
            int j = tid + i * 128;                                                 \
            int kr = j >> 4;                                                       \
            int nf = (j & 15) * 4;                                                 \
            br[i] = *(const float4*)(Wp + (size_t)(kb + kr) * DOUT + n0col + nf);  \
        }                                                                          \
    } while (0)

#define STS(bufb)                                                                  \
    do {                                                                           \
        for (int i = 0; i < 2; i++) {                                              \
            int j = tid + i * 128;                                                 \
            int row = j >> 2;                                                      \
            int kf = (j & 3) * 4;                                                  \
            float* p = &As[bufb][row * ASTR + kf];                                 \
            p[0] = f2tf(ar[i].x); p[1] = f2tf(ar[i].y);                            \
            p[2] = f2tf(ar[i].z); p[3] = f2tf(ar[i].w);                            \
        }                                                                          \
        for (int i = 0; i < 2; i++) {                                              \
            int j = tid + i * 128;                                                 \
            int kr = j >> 4;                                                       \
            int nf = (j & 15) * 4;                                                 \
            float* p = &Bs[bufb][kr * BSTR + nf];                                  \
            p[0] = f2tf(br[i].x); p[1] = f2tf(br[i].y);                            \
            p[2] = f2tf(br[i].z); p[3] = f2tf(br[i].w);                            \
        }                                                                          \
    } while (0)

    GLOAD(0);
    STS(0);

    for (int it = 0; it < KITERS; ++it) {
        __syncthreads();
        if (it + 1 < KITERS) GLOAD(it + 1);

        const int bf = it & 1;
#pragma unroll
        for (int ko = 0; ko < BKT; ko += 8) {
            unsigned af[2][4];
#pragma unroll
            for (int mf = 0; mf < 2; mf++) {
                int r0 = wm + mf * 16 + g;
                af[mf][0] = __float_as_uint(As[bf][r0 * ASTR + ko + t]);
                af[mf][1] = __float_as_uint(As[bf][(r0 + 8) * ASTR + ko + t]);
                af[mf][2] = __float_as_uint(As[bf][r0 * ASTR + ko + t + 4]);
                af[mf][3] = __float_as_uint(As[bf][(r0 + 8) * ASTR + ko + t + 4]);
            }
            unsigned bfr[4][2];
#pragma unroll
            for (int nf = 0; nf < 4; nf++) {
                int c0 = wn + nf * 8 + g;
                bfr[nf][0] = __float_as_uint(Bs[bf][(ko + t) * BSTR + c0]);
                bfr[nf][1] = __float_as_uint(Bs[bf][(ko + t + 4) * BSTR + c0]);
            }
#pragma unroll
            for (int mf = 0; mf < 2; mf++)
#pragma unroll
                for (int nf = 0; nf < 4; nf++)
                    MMA_TF32(acc[mf][nf], af[mf], bfr[nf][0], bfr[nf][1]);
        }

        if (it + 1 < KITERS) STS((it + 1) & 1);
    }

    // Epilogue: write partial tile (deterministic, no atomics)
    float* yp = g_Ypart + (size_t)z * (BB * Y_N);
#pragma unroll
    for (int mf = 0; mf < 2; mf++) {
#pragma unroll
        for (int nf = 0; nf < 4; nf++) {
            int row = m0 + wm + mf * 16 + g;
            int col = nt * BNT + wn + nf * 8 + 2 * t;
            float2 v0 = make_float2(acc[mf][nf][0], acc[mf][nf][1]);
            float2 v1 = make_float2(acc[mf][nf][2], acc[mf][nf][3]);
            *(float2*)(yp + (size_t)row * Y_N + col) = v0;
            *(float2*)(yp + (size_t)(row + 8) * Y_N + col) = v1;
        }
    }
#undef GLOAD
#undef STS
}

// ---------------------------------------------------------------------------
// K1b: reduce split-K partials, add bias, apply sigmoid for e/a
// ---------------------------------------------------------------------------
__global__ void reduce_act_kernel(const float* __restrict__ bk,
                                  const float* __restrict__ be,
                                  const float* __restrict__ ba)
{
    int idx = blockIdx.x * blockDim.x + threadIdx.x;  // < 294912
    float s = 0.0f;
#pragma unroll
    for (int z = 0; z < SPLITK; z++)
        s += g_Ypart[(size_t)z * (BB * Y_N) + idx];
    int row = idx / Y_N;
    int col = idx - row * Y_N;
    int mat = col / DOUT;
    int c = col - mat * DOUT;
    if (mat == 0) {
        g_Ks[row * DOUT + c] = s + bk[c];
    } else if (mat == 1) {
        float v = s + be[c];
        g_Es[row * DOUT + c] = 1.0f / (1.0f + __expf(-v));
    } else {
        float v = s + ba[c];
        g_As[row * DOUT + c] = 1.0f / (1.0f + __expf(-v));
    }
}

// ---------------------------------------------------------------------------
// K2: per-batch fused cosine addressing + softmax + memory update
// grid 256, 512 threads, ~193 KB dynamic smem
// ---------------------------------------------------------------------------
#define TILE_ROWS 512
#define TSTR 17   // float4 stride per row (68 floats -> conflict-free LDS.128)
#define SMEM_FLOATS (TILE_ROWS * 68 + HH * NN + 3 * DOUT + 32)

__global__ __launch_bounds__(512, 1) void attn_update_kernel(
    const float* __restrict__ memory, float* __restrict__ out_mem,
    float* __restrict__ out_w)
{
    extern __shared__ float sm[];
    float* tile    = sm;                       // 512*68 = 34816
    float* scores  = tile + TILE_ROWS * 68;    // 6*2048 = 12288
    float* kn      = scores + HH * NN;         // 384
    float* esm     = kn + DOUT;                // 384
    float* asm_    = esm + DOUT;               // 384
    float* red     = asm_ + DOUT;              // 32

    const int b = blockIdx.x;
    const int tid = threadIdx.x, wid = tid >> 5, lane = tid & 31;

    // Phase 0: load e/a, compute normalized k
    if (tid < DOUT) {
        esm[tid]  = g_Es[b * DOUT + tid];
        asm_[tid] = g_As[b * DOUT + tid];
    }
    if (wid < HH) {
        float k0 = g_Ks[b * DOUT + wid * 64 + 2 * lane];
        float k1 = g_Ks[b * DOUT + wid * 64 + 2 * lane + 1];
        float ss = k0 * k0 + k1 * k1;
#pragma unroll
        for (int o = 16; o > 0; o >>= 1) ss += __shfl_xor_sync(0xffffffffu, ss, o);
        float rn = rsqrtf(ss);
        kn[wid * 64 + 2 * lane]     = k0 * rn;
        kn[wid * 64 + 2 * lane + 1] = k1 * rn;
    }
    __syncthreads();

    const float* __restrict__ memb = memory + (size_t)b * MEM_ELEMS;
    float4* tf4 = (float4*)tile;

    // Phase 1: scores[h][n] = cos(k_h, mem_n)
    for (int tl = 0; tl < 4; ++tl) {
        const float4* src = (const float4*)(memb + tl * (TILE_ROWS * MM));
#pragma unroll
        for (int i = 0; i < 16; i++) {
            int j = tid + i * 512;
            tf4[(j >> 4) * TSTR + (j & 15)] = src[j];
        }
        __syncthreads();
        {
            float ss = 0.0f;
            float d[HH];
#pragma unroll
            for (int h = 0; h < HH; h++) d[h] = 0.0f;
            const float4* rp = tf4 + tid * TSTR;
#pragma unroll
            for (int q = 0; q < 16; q++) {
                float4 v = rp[q];
                ss += v.x * v.x + v.y * v.y + v.z * v.z + v.w * v.w;
#pragma unroll
                for (int h = 0; h < HH; h++) {
                    float4 kv = *(const float4*)(kn + h * 64 + q * 4);
                    d[h] += v.x * kv.x + v.y * kv.y + v.z * kv.z + v.w * kv.w;
                }
            }
            float rn = rsqrtf(ss);
            int n = tl * TILE_ROWS + tid;
#pragma unroll
            for (int h = 0; h < HH; h++) scores[h * NN + n] = d[h] * rn;
        }
        __syncthreads();
    }

    // Phase 2: softmax over n per head; write w_new; keep weights in smem
    for (int h = 0; h < HH; h++) {
        float* sc = scores + h * NN;
        float mx = -1e30f;
        for (int i = tid; i < NN; i += 512) mx = fmaxf(mx, sc[i]);
#pragma unroll
        for (int o = 16; o > 0; o >>= 1) mx = fmaxf(mx, __shfl_xor_sync(0xffffffffu, mx, o));
        if (lane == 0) red[wid] = mx;
        __syncthreads();
        if (tid < 16) {
            float v = red[tid];
#pragma unroll
            for (int o = 8; o > 0; o >>= 1) v = fmaxf(v, __shfl_xor_sync(0xffffu, v, o));
            if (tid == 0) red[0] = v;
        }
        __syncthreads();
        mx = red[0];
        __syncthreads();

        float sum = 0.0f;
        for (int i = tid; i < NN; i += 512) {
            float e = __expf(sc[i] - mx);
            sc[i] = e;
            sum += e;
        }
#pragma unroll
        for (int o = 16; o > 0; o >>= 1) sum += __shfl_xor_sync(0xffffffffu, sum, o);
        if (lane == 0) red[wid] = sum;
        __syncthreads();
        if (tid < 16) {
            float v = red[tid];
#pragma unroll
            for (int o = 8; o > 0; o >>= 1) v += __shfl_xor_sync(0xffffu, v, o);
            if (tid == 0) red[0] = v;
        }
        __syncthreads();
        float inv = 1.0f / red[0];
        __syncthreads();

        for (int i = tid; i < NN; i += 512) {
            float wv = sc[i] * inv;
            sc[i] = wv;
            out_w[(size_t)b * (HH * NN) + h * NN + i] = wv;
        }
    }
    __syncthreads();

    // Phase 3: new_mem = m - m*m*erase + add   (warp per row, e/a hoisted)
    float eh0[HH], eh1[HH], ah0[HH], ah1[HH];
#pragma unroll
    for (int h = 0; h < HH; h++) {
        eh0[h] = esm[h * 64 + 2 * lane];
        eh1[h] = esm[h * 64 + 2 * lane + 1];
        ah0[h] = asm_[h * 64 + 2 * lane];
        ah1[h] = asm_[h * 64 + 2 * lane + 1];
    }
    float* outm = out_mem + (size_t)b * MEM_ELEMS;
    for (int n = wid; n < NN; n += 16) {
        float2 mv = *(const float2*)(memb + n * MM + 2 * lane);
        float er0 = 0.f, er1 = 0.f, ad0 = 0.f, ad1 = 0.f;
#pragma unroll
        for (int h = 0; h < HH; h++) {
            float wv = scores[h * NN + n];
            er0 += wv * eh0[h];
            er1 += wv * eh1[h];
            ad0 += wv * ah0[h];
            ad1 += wv * ah1[h];
        }
        float2 ov;
        ov.x = mv.x - mv.x * mv.x * er0 + ad0;
        ov.y = mv.y - mv.y * mv.y * er1 + ad1;
        *(float2*)(outm + n * MM + 2 * lane) = ov;
    }
}

// ---------------------------------------------------------------------------
extern "C" void kernel_launch(void* const* d_in, const int* in_sizes, int n_in,
                              void* d_out, int out_size)
{
    const float* inputs = (const float*)d_in[0];
    const float* memory = (const float*)d_in[1];
    const float* w      = (const float*)d_in[2];
    const float* Wk     = (const float*)d_in[3];
    const float* bk     = (const float*)d_in[4];
    const float* We     = (const float*)d_in[5];
    const float* be     = (const float*)d_in[6];
    const float* Wa     = (const float*)d_in[7];
    const float* ba     = (const float*)d_in[8];

    float* out     = (float*)d_out;
    float* out_mem = out;                       // new_memory [B,N,M]
    float* out_w   = out + OUT_MEM_TOTAL;       // w_new      [B,H,N]

    dim3 g1(4, 18, SPLITK);
    gemm_kernel<<<g1, 128>>>(w, inputs, Wk, We, Wa);

    reduce_act_kernel<<<(BB * Y_N) / 256, 256>>>(bk, be, ba);

    const int smem_bytes = SMEM_FLOATS * (int)sizeof(float);
    cudaFuncSetAttribute(attn_update_kernel,
                         cudaFuncAttributeMaxDynamicSharedMemorySize, smem_bytes);
    attn_update_kernel<<<BB, 512, smem_bytes>>>(memory, out_mem, out_w);
}